// round 6
// baseline (speedup 1.0000x reference)
#include <cuda_runtime.h>
#include <cuda_bf16.h>
#include <cstdint>

// Perceive3D: out[b, k*16+c, z, h, w], k in {identity, d/dW, d/dH, d/dD} (Sobel-smoothed, /16),
// replicate padding. Separable: s=[1,2,1], d=[-1,0,1].
//
// R6: barrier-free. No SMEM, no cp.async, no __syncthreads. Each warp owns one H row
// (32 lanes x 2 W voxels), loads rows h-1,h,h+1 itself (L1/L2 absorb the 3x re-read),
// W-neighbors via warp shuffles (lane-clamped = edge padding), z via 3-deep register
// rotation with a double-buffered register prefetch of plane z+2.

#define ZLEN 16

__global__ __launch_bounds__(256, 5)
void perceive3d_kernel(const float* __restrict__ x, float* __restrict__ out) {
    const int lx = threadIdx.x;            // 0..31 -> W pair (2lx, 2lx+1)
    const int ly = threadIdx.y;            // 0..7  -> H row within tile (1 warp = 1 row)
    const int h  = blockIdx.x * 8 + ly;
    const int bc = blockIdx.y;             // 0..63 = b*16+c
    const int z0 = blockIdx.z * ZLEN;
    const int b  = bc >> 4;
    const int c  = bc & 15;

    const size_t cstride = (size_t)64 * 64 * 64;
    const float* __restrict__ xin = x + (size_t)bc * cstride;
    float* __restrict__ out0 = out + ((size_t)(b * 64) + c) * cstride;

    const int hm = (h == 0)  ? 0  : h - 1;
    const int hp = (h == 63) ? 63 : h + 1;
    const int col = 2 * lx;
    const float* __restrict__ rm = xin + hm * 64 + col;
    const float* __restrict__ rc = xin + (size_t)h * 64 + col;
    const float* __restrict__ rp = xin + hp * 64 + col;
    const int line = h * 64 + col;

    // load the 3 H rows of plane z (z-clamped) for this thread's W pair
    auto loadPlane = [&](int z, float2& vm, float2& vc, float2& vp) {
        int zz = z < 0 ? 0 : (z > 63 ? 63 : z);
        const size_t off = (size_t)zz * 4096;
        vm = *(const float2*)(rm + off);
        vc = *(const float2*)(rc + off);
        vp = *(const float2*)(rp + off);
    };

    // W-direction row stats for a float2 of adjacent voxels:
    //   sw = [1,2,1] smoothing, dw = [-1,0,1] derivative; lane-clamped edges.
    auto rowstat = [&](float2 v, float2& sw, float2& dw) {
        float cl = __shfl_up_sync(0xffffffffu, v.y, 1);   // col-1 (left neighbor's .y)
        float cr = __shfl_down_sync(0xffffffffu, v.x, 1); // col+2 (right neighbor's .x)
        if (lx == 0)  cl = v.x;   // replicate at W=0
        if (lx == 31) cr = v.y;   // replicate at W=63
        sw.x = cl  + 2.f * v.x + v.y;
        sw.y = v.x + 2.f * v.y + cr;
        dw.x = v.y - cl;
        dw.y = cr  - v.x;
    };

    // plane stats: P = s(h)s(w), QW = s(h)d(w), QH = d(h)s(w), CC = center
    auto stats = [&](float2 vm, float2 vc, float2 vp,
                     float2& P, float2& QW, float2& QH, float2& CC) {
        float2 swm, dwm, swc, dwc, swp, dwp;
        rowstat(vm, swm, dwm);
        rowstat(vc, swc, dwc);
        rowstat(vp, swp, dwp);
        P.x  = swm.x + 2.f * swc.x + swp.x;   P.y  = swm.y + 2.f * swc.y + swp.y;
        QW.x = dwm.x + 2.f * dwc.x + dwp.x;   QW.y = dwm.y + 2.f * dwc.y + dwp.y;
        QH.x = swp.x - swm.x;                 QH.y = swp.y - swm.y;
        CC   = vc;
    };

    // emit all four outputs for plane z
    auto emit = [&](int z, float2 Pp, float2 Pn,
                    float2 Xp, float2 Xc, float2 Xn,
                    float2 Yp, float2 Yc, float2 Yn, float2 Cc) {
        float2 sx, sy, sz;
        sx.x = (Xp.x + 2.f * Xc.x + Xn.x) * 0.0625f;
        sx.y = (Xp.y + 2.f * Xc.y + Xn.y) * 0.0625f;
        sy.x = (Yp.x + 2.f * Yc.x + Yn.x) * 0.0625f;
        sy.y = (Yp.y + 2.f * Yc.y + Yn.y) * 0.0625f;
        sz.x = (Pn.x - Pp.x) * 0.0625f;
        sz.y = (Pn.y - Pp.y) * 0.0625f;
        const size_t o = (size_t)z * 4096 + line;
        __stcs((float2*)(out0 + o),                Cc);
        __stcs((float2*)(out0 + o + 16 * cstride), sx);
        __stcs((float2*)(out0 + o + 32 * cstride), sy);
        __stcs((float2*)(out0 + o + 48 * cstride), sz);
    };

    float2 Am, Ac, Ap, Bm, Bc, Bp;                       // raw plane double buffer
    float2 Pp, Pc, Pn, Xp, Xc, Xn, Yp, Yc, Yn, Cc, Cn;   // z stat rotation

    // prologue: planes z0-1, z0 -> stats; plane z0+1 staged in A
    loadPlane(z0 - 1, Am, Ac, Ap);
    stats(Am, Ac, Ap, Pp, Xp, Yp, Cn);
    loadPlane(z0, Am, Ac, Ap);
    stats(Am, Ac, Ap, Pc, Xc, Yc, Cc);
    loadPlane(z0 + 1, Am, Ac, Ap);

    #pragma unroll
    for (int t = 0; t < ZLEN; t += 2) {
        // even step: prefetch z+2 into B, consume A (= plane z+1)
        loadPlane(z0 + t + 2, Bm, Bc, Bp);
        stats(Am, Ac, Ap, Pn, Xn, Yn, Cn);
        emit(z0 + t, Pp, Pn, Xp, Xc, Xn, Yp, Yc, Yn, Cc);
        Pp = Pc; Pc = Pn;  Xp = Xc; Xc = Xn;  Yp = Yc; Yc = Yn;  Cc = Cn;

        // odd step: prefetch z+3 into A, consume B (= plane z+2)
        loadPlane(z0 + t + 3, Am, Ac, Ap);
        stats(Bm, Bc, Bp, Pn, Xn, Yn, Cn);
        emit(z0 + t + 1, Pp, Pn, Xp, Xc, Xn, Yp, Yc, Yn, Cc);
        Pp = Pc; Pc = Pn;  Xp = Xc; Xc = Xn;  Yp = Yc; Yc = Yn;  Cc = Cn;
    }
}

extern "C" void kernel_launch(void* const* d_in, const int* in_sizes, int n_in,
                              void* d_out, int out_size) {
    const float* x = (const float*)d_in[0];
    // d_in[1] = kernels (4x3x3x3) — fixed separable stencils folded into the kernel.
    float* out = (float*)d_out;

    dim3 grid(8, 64, 64 / ZLEN);   // (8 H tiles, B*C=64, 4 z chunks) = 2048 blocks
    dim3 block(32, 8);             // 256 threads, warp = one H row
    perceive3d_kernel<<<grid, block>>>(x, out);
}

// round 7
// speedup vs baseline: 1.0357x; 1.0357x over previous
#include <cuda_runtime.h>
#include <cuda_bf16.h>
#include <cstdint>

// Perceive3D: out[b, k*16+c, z, h, w], k in {identity, d/dW, d/dH, d/dD} (Sobel-smoothed, /16),
// replicate padding. Separable: s=[1,2,1], d=[-1,0,1].
//
// R7: barrier-free warp-per-row skeleton (R6) with
//  - vertical-first stats: per-thread column sums sv/dv, then ONE horizontal pass
//    (4 shuffles/plane instead of 6, shuffled sv reused for both P and QW),
//  - __launch_bounds__(256,6) -> 48-warp/SM occupancy ceiling,
//  - ZLEN=8 (4096 blocks) for finer wave granularity.

#define ZLEN 8

__global__ __launch_bounds__(256, 6)
void perceive3d_kernel(const float* __restrict__ x, float* __restrict__ out) {
    const int lx = threadIdx.x;            // 0..31 -> W pair (2lx, 2lx+1)
    const int ly = threadIdx.y;            // 0..7  -> H row within tile (1 warp = 1 row)
    const int h  = blockIdx.x * 8 + ly;
    const int bc = blockIdx.y;             // 0..63 = b*16+c
    const int z0 = blockIdx.z * ZLEN;
    const int b  = bc >> 4;
    const int c  = bc & 15;

    const size_t cstride = (size_t)64 * 64 * 64;
    const float* __restrict__ xin = x + (size_t)bc * cstride;
    float* __restrict__ out0 = out + ((size_t)(b * 64) + c) * cstride;

    const int hm = (h == 0)  ? 0  : h - 1;
    const int hp = (h == 63) ? 63 : h + 1;
    const int col = 2 * lx;
    const float* __restrict__ rm = xin + hm * 64 + col;
    const float* __restrict__ rc = xin + (size_t)h * 64 + col;
    const float* __restrict__ rp = xin + hp * 64 + col;
    const int line = h * 64 + col;

    // load the 3 H rows of plane z (z-clamped) for this thread's W pair
    auto loadPlane = [&](int z, float2& vm, float2& vc, float2& vp) {
        int zz = z < 0 ? 0 : (z > 63 ? 63 : z);
        const size_t off = (size_t)zz * 4096;
        vm = *(const float2*)(rm + off);
        vc = *(const float2*)(rc + off);
        vp = *(const float2*)(rp + off);
    };

    // plane stats, vertical-first:
    //   sv = vm + 2vc + vp (H-smooth), dv = vp - vm (H-deriv), then one horizontal
    //   shuffle pass; shuffled sv serves both P (s⊗s) and QW (s⊗d).
    auto stats = [&](float2 vm, float2 vc, float2 vp,
                     float2& P, float2& QW, float2& QH, float2& CC) {
        float2 sv, dv;
        sv.x = vm.x + 2.f * vc.x + vp.x;  sv.y = vm.y + 2.f * vc.y + vp.y;
        dv.x = vp.x - vm.x;               dv.y = vp.y - vm.y;
        float svL = __shfl_up_sync(0xffffffffu,  sv.y, 1);  // col-1
        float svR = __shfl_down_sync(0xffffffffu, sv.x, 1); // col+2
        float dvL = __shfl_up_sync(0xffffffffu,  dv.y, 1);
        float dvR = __shfl_down_sync(0xffffffffu, dv.x, 1);
        if (lx == 0)  { svL = sv.x; dvL = dv.x; }   // replicate at W=0
        if (lx == 31) { svR = sv.y; dvR = dv.y; }   // replicate at W=63
        P.x  = svL  + 2.f * sv.x + sv.y;   P.y  = sv.x + 2.f * sv.y + svR;
        QW.x = sv.y - svL;                 QW.y = svR  - sv.x;
        QH.x = dvL  + 2.f * dv.x + dv.y;   QH.y = dv.x + 2.f * dv.y + dvR;
        CC   = vc;
    };

    // emit all four outputs for plane z
    auto emit = [&](int z, float2 Pp, float2 Pn,
                    float2 Xp, float2 Xc, float2 Xn,
                    float2 Yp, float2 Yc, float2 Yn, float2 Cc) {
        float2 sx, sy, sz;
        sx.x = (Xp.x + 2.f * Xc.x + Xn.x) * 0.0625f;
        sx.y = (Xp.y + 2.f * Xc.y + Xn.y) * 0.0625f;
        sy.x = (Yp.x + 2.f * Yc.x + Yn.x) * 0.0625f;
        sy.y = (Yp.y + 2.f * Yc.y + Yn.y) * 0.0625f;
        sz.x = (Pn.x - Pp.x) * 0.0625f;
        sz.y = (Pn.y - Pp.y) * 0.0625f;
        const size_t o = (size_t)z * 4096 + line;
        __stcs((float2*)(out0 + o),                Cc);
        __stcs((float2*)(out0 + o + 16 * cstride), sx);
        __stcs((float2*)(out0 + o + 32 * cstride), sy);
        __stcs((float2*)(out0 + o + 48 * cstride), sz);
    };

    float2 Am, Ac, Ap, Bm, Bc, Bp;                       // raw plane double buffer
    float2 Pp, Pc, Pn, Xp, Xc, Xn, Yp, Yc, Yn, Cc, Cn;   // z stat rotation

    // prologue: planes z0-1, z0 -> stats; plane z0+1 staged in A
    loadPlane(z0 - 1, Am, Ac, Ap);
    stats(Am, Ac, Ap, Pp, Xp, Yp, Cn);
    loadPlane(z0, Am, Ac, Ap);
    stats(Am, Ac, Ap, Pc, Xc, Yc, Cc);
    loadPlane(z0 + 1, Am, Ac, Ap);

    #pragma unroll
    for (int t = 0; t < ZLEN; t += 2) {
        // even step: prefetch z+2 into B, consume A (= plane z+1)
        loadPlane(z0 + t + 2, Bm, Bc, Bp);
        stats(Am, Ac, Ap, Pn, Xn, Yn, Cn);
        emit(z0 + t, Pp, Pn, Xp, Xc, Xn, Yp, Yc, Yn, Cc);
        Pp = Pc; Pc = Pn;  Xp = Xc; Xc = Xn;  Yp = Yc; Yc = Yn;  Cc = Cn;

        // odd step: prefetch z+3 into A, consume B (= plane z+2)
        loadPlane(z0 + t + 3, Am, Ac, Ap);
        stats(Bm, Bc, Bp, Pn, Xn, Yn, Cn);
        emit(z0 + t + 1, Pp, Pn, Xp, Xc, Xn, Yp, Yc, Yn, Cc);
        Pp = Pc; Pc = Pn;  Xp = Xc; Xc = Xn;  Yp = Yc; Yc = Yn;  Cc = Cn;
    }
}

extern "C" void kernel_launch(void* const* d_in, const int* in_sizes, int n_in,
                              void* d_out, int out_size) {
    const float* x = (const float*)d_in[0];
    // d_in[1] = kernels (4x3x3x3) — fixed separable stencils folded into the kernel.
    float* out = (float*)d_out;

    dim3 grid(8, 64, 64 / ZLEN);   // (8 H tiles, B*C=64, 8 z chunks) = 4096 blocks
    dim3 block(32, 8);             // 256 threads, warp = one H row
    perceive3d_kernel<<<grid, block>>>(x, out);
}